// round 1
// baseline (speedup 1.0000x reference)
#include <cuda_runtime.h>
#include <cstdint>

// Problem constants
#define Bq  32
#define Lq  512
#define Dq  4096
#define Hq  32
#define HDq 128
#define BLq (Bq*Lq)     // 16384
#define BHq (Bq*Hq)     // 1024

// ---------------- scratch (device globals; no allocations) ----------------
__device__ float g_xr[(size_t)BLq*Dq];          // tf32-rounded x          (268 MB)
__device__ float g_W [4][(size_t)Dq*Dq];        // tf32-rounded Wq,Wk,Wv,Wo (268 MB)
__device__ float g_q [(size_t)BHq*Lq*HDq];      // Q  [b,h,l,hd]
__device__ float g_k [(size_t)BHq*Lq*HDq];      // K
__device__ float g_v [(size_t)BHq*Lq*HDq];      // V
__device__ float g_s [(size_t)BHq*Lq*Lq];       // scores / probs (1 GB)
__device__ float g_ao[(size_t)BLq*Dq];          // attn out [b,l,h,hd]

// ---------------- helpers ----------------
__device__ __forceinline__ float tf32f(float x) {
    uint32_t u;
    asm("cvt.rna.tf32.f32 %0, %1;" : "=r"(u) : "f"(x));
    return __uint_as_float(u);
}

__device__ __forceinline__ void cp_async16(void* smem, const void* gmem) {
    uint32_t s = (uint32_t)__cvta_generic_to_shared(smem);
    asm volatile("cp.async.cg.shared.global [%0], [%1], 16;\n" :: "r"(s), "l"(gmem));
}
#define CP_COMMIT asm volatile("cp.async.commit_group;\n" ::: "memory")
#define CP_WAIT0  asm volatile("cp.async.wait_group 0;\n" ::: "memory")

__device__ __forceinline__ void mma_tf32(float* c, const uint32_t* a, const uint32_t* b) {
    asm volatile(
        "mma.sync.aligned.m16n8k8.row.col.f32.tf32.tf32.f32 "
        "{%0,%1,%2,%3},{%4,%5,%6,%7},{%8,%9},{%0,%1,%2,%3};"
        : "+f"(c[0]), "+f"(c[1]), "+f"(c[2]), "+f"(c[3])
        : "r"(a[0]), "r"(a[1]), "r"(a[2]), "r"(a[3]),
          "r"(b[0]), "r"(b[1]));
}

// ---------------- round-to-tf32 copy (prepass) ----------------
__global__ void roundcpy_k(const float4* __restrict__ src, int which, long n4) {
    float* dstf = (which == 0) ? g_xr : g_W[which - 1];
    float4* dst = reinterpret_cast<float4*>(dstf);
    for (long i = (long)blockIdx.x * blockDim.x + threadIdx.x; i < n4;
         i += (long)gridDim.x * blockDim.x) {
        float4 t = src[i];
        t.x = tf32f(t.x); t.y = tf32f(t.y); t.z = tf32f(t.z); t.w = tf32f(t.w);
        dst[i] = t;
    }
}

// ==========================================================================
// linear_k: C[16384,4096] = A @ W^T + bias
// which: 0/1/2 -> Q/K/V (output written head-split, tf32-rounded)
//        3     -> final output (raw fp32 to outp)
// Block 128x128, K-step 16, 256 threads (8 warps = 4x2), warp tile 32x64.
// ==========================================================================
__global__ __launch_bounds__(256) void linear_k(const float* __restrict__ bias,
                                                float* __restrict__ outp, int which) {
    __shared__ float As[2][128 * 20];
    __shared__ float Bs[2][128 * 20];

    const float* A  = (which < 3) ? g_xr : g_ao;
    const float* Wm = g_W[which];
    const int K  = Dq;
    const int m0 = blockIdx.y * 128;
    const int n0 = blockIdx.x * 128;
    const int tid  = threadIdx.x;
    const int lane = tid & 31, warp = tid >> 5;
    const int wm = warp >> 1, wn = warp & 1;
    const int lr = lane >> 2, lc = lane & 3;

    // loader: 512 float4 per tile over 256 threads -> 2 each
    const int r0 = tid >> 2, c0 = (tid & 3) * 4;
    const int r1 = r0 + 64;

    float acc[2][8][4];
#pragma unroll
    for (int i = 0; i < 2; i++)
#pragma unroll
        for (int j = 0; j < 8; j++)
#pragma unroll
            for (int t = 0; t < 4; t++) acc[i][j][t] = 0.f;

    {   // prologue: stage 0
        const float* ga = A  + (size_t)m0 * K;
        const float* gb = Wm + (size_t)n0 * K;
        cp_async16(&As[0][r0 * 20 + c0], ga + (size_t)r0 * K + c0);
        cp_async16(&As[0][r1 * 20 + c0], ga + (size_t)r1 * K + c0);
        cp_async16(&Bs[0][r0 * 20 + c0], gb + (size_t)r0 * K + c0);
        cp_async16(&Bs[0][r1 * 20 + c0], gb + (size_t)r1 * K + c0);
        CP_COMMIT;
    }

    const int nkt = K / 16;  // 256
    int buf = 0;
    for (int kt = 0; kt < nkt; ++kt) {
        CP_WAIT0;
        __syncthreads();
        if (kt + 1 < nkt) {
            const int kb = (kt + 1) * 16;
            const float* ga = A  + (size_t)m0 * K + kb;
            const float* gb = Wm + (size_t)n0 * K + kb;
            const int nb = buf ^ 1;
            cp_async16(&As[nb][r0 * 20 + c0], ga + (size_t)r0 * K + c0);
            cp_async16(&As[nb][r1 * 20 + c0], ga + (size_t)r1 * K + c0);
            cp_async16(&Bs[nb][r0 * 20 + c0], gb + (size_t)r0 * K + c0);
            cp_async16(&Bs[nb][r1 * 20 + c0], gb + (size_t)r1 * K + c0);
            CP_COMMIT;
        }
        const uint32_t* as = (const uint32_t*)As[buf];
        const uint32_t* bs = (const uint32_t*)Bs[buf];
#pragma unroll
        for (int kk = 0; kk < 16; kk += 8) {
            uint32_t af[2][4], bf[8][2];
#pragma unroll
            for (int mf = 0; mf < 2; mf++) {
                const int r = wm * 32 + mf * 16 + lr;
                af[mf][0] = as[r * 20 + kk + lc];
                af[mf][1] = as[(r + 8) * 20 + kk + lc];
                af[mf][2] = as[r * 20 + kk + lc + 4];
                af[mf][3] = as[(r + 8) * 20 + kk + lc + 4];
            }
#pragma unroll
            for (int nf = 0; nf < 8; nf++) {
                const int c = wn * 64 + nf * 8 + lr;
                bf[nf][0] = bs[c * 20 + kk + lc];
                bf[nf][1] = bs[c * 20 + kk + lc + 4];
            }
#pragma unroll
            for (int mf = 0; mf < 2; mf++)
#pragma unroll
                for (int nf = 0; nf < 8; nf++) mma_tf32(acc[mf][nf], af[mf], bf[nf]);
        }
        buf ^= 1;
    }

    // epilogue
#pragma unroll
    for (int mf = 0; mf < 2; mf++) {
#pragma unroll
        for (int nf = 0; nf < 8; nf++) {
            const int row = m0 + wm * 32 + mf * 16 + lr;
            const int col = n0 + wn * 64 + nf * 8 + lc * 2;
            const float b0 = bias[col], b1 = bias[col + 1];
#pragma unroll
            for (int rr = 0; rr < 2; rr++) {
                const int r = row + rr * 8;
                const float v0 = acc[mf][nf][rr * 2 + 0] + b0;
                const float v1 = acc[mf][nf][rr * 2 + 1] + b1;
                if (which < 3) {
                    float* dst = (which == 0) ? g_q : (which == 1) ? g_k : g_v;
                    const int b = r >> 9, l = r & 511;
                    const int h = col >> 7, hd = col & 127;
                    const size_t idx = (((size_t)b * Hq + h) * Lq + l) * HDq + hd;
                    dst[idx]     = tf32f(v0);
                    dst[idx + 1] = tf32f(v1);
                } else {
                    const size_t idx = (size_t)r * Dq + col;
                    outp[idx]     = v0;
                    outp[idx + 1] = v1;
                }
            }
        }
    }
}

// ==========================================================================
// scores_k: S[bh] = (Q[bh] @ K[bh]^T) / sqrt(HD). M=N=512, K=128 per batch.
// Fully-masked tiles (n0 > m0+127) are skipped.
// ==========================================================================
__global__ __launch_bounds__(256) void scores_k() {
    const int bh = blockIdx.z;
    const int m0 = blockIdx.y * 128, n0 = blockIdx.x * 128;
    if (n0 > m0 + 127) return;  // entirely above causal diagonal

    __shared__ float As[2][128 * 20];
    __shared__ float Bs[2][128 * 20];

    const float* A  = g_q + (size_t)bh * Lq * HDq;
    const float* Bm = g_k + (size_t)bh * Lq * HDq;
    const int K = HDq;  // 128

    const int tid  = threadIdx.x;
    const int lane = tid & 31, warp = tid >> 5;
    const int wm = warp >> 1, wn = warp & 1;
    const int lr = lane >> 2, lc = lane & 3;
    const int r0 = tid >> 2, c0 = (tid & 3) * 4;
    const int r1 = r0 + 64;

    float acc[2][8][4];
#pragma unroll
    for (int i = 0; i < 2; i++)
#pragma unroll
        for (int j = 0; j < 8; j++)
#pragma unroll
            for (int t = 0; t < 4; t++) acc[i][j][t] = 0.f;

    {
        const float* ga = A  + (size_t)m0 * K;
        const float* gb = Bm + (size_t)n0 * K;
        cp_async16(&As[0][r0 * 20 + c0], ga + (size_t)r0 * K + c0);
        cp_async16(&As[0][r1 * 20 + c0], ga + (size_t)r1 * K + c0);
        cp_async16(&Bs[0][r0 * 20 + c0], gb + (size_t)r0 * K + c0);
        cp_async16(&Bs[0][r1 * 20 + c0], gb + (size_t)r1 * K + c0);
        CP_COMMIT;
    }

    const int nkt = K / 16;  // 8
    int buf = 0;
    for (int kt = 0; kt < nkt; ++kt) {
        CP_WAIT0;
        __syncthreads();
        if (kt + 1 < nkt) {
            const int kb = (kt + 1) * 16;
            const float* ga = A  + (size_t)m0 * K + kb;
            const float* gb = Bm + (size_t)n0 * K + kb;
            const int nb = buf ^ 1;
            cp_async16(&As[nb][r0 * 20 + c0], ga + (size_t)r0 * K + c0);
            cp_async16(&As[nb][r1 * 20 + c0], ga + (size_t)r1 * K + c0);
            cp_async16(&Bs[nb][r0 * 20 + c0], gb + (size_t)r0 * K + c0);
            cp_async16(&Bs[nb][r1 * 20 + c0], gb + (size_t)r1 * K + c0);
            CP_COMMIT;
        }
        const uint32_t* as = (const uint32_t*)As[buf];
        const uint32_t* bs = (const uint32_t*)Bs[buf];
#pragma unroll
        for (int kk = 0; kk < 16; kk += 8) {
            uint32_t af[2][4], bf[8][2];
#pragma unroll
            for (int mf = 0; mf < 2; mf++) {
                const int r = wm * 32 + mf * 16 + lr;
                af[mf][0] = as[r * 20 + kk + lc];
                af[mf][1] = as[(r + 8) * 20 + kk + lc];
                af[mf][2] = as[r * 20 + kk + lc + 4];
                af[mf][3] = as[(r + 8) * 20 + kk + lc + 4];
            }
#pragma unroll
            for (int nf = 0; nf < 8; nf++) {
                const int c = wn * 64 + nf * 8 + lr;
                bf[nf][0] = bs[c * 20 + kk + lc];
                bf[nf][1] = bs[c * 20 + kk + lc + 4];
            }
#pragma unroll
            for (int mf = 0; mf < 2; mf++)
#pragma unroll
                for (int nf = 0; nf < 8; nf++) mma_tf32(acc[mf][nf], af[mf], bf[nf]);
        }
        buf ^= 1;
    }

    const float scale = 0.0883883476483184405501f;  // 1/sqrt(128)
    float* Sb = g_s + (size_t)bh * Lq * Lq;
#pragma unroll
    for (int mf = 0; mf < 2; mf++) {
#pragma unroll
        for (int nf = 0; nf < 8; nf++) {
            const int row = m0 + wm * 32 + mf * 16 + lr;
            const int col = n0 + wn * 64 + nf * 8 + lc * 2;
#pragma unroll
            for (int rr = 0; rr < 2; rr++) {
                const int r = row + rr * 8;
                Sb[(size_t)r * Lq + col]     = acc[mf][nf][rr * 2 + 0] * scale;
                Sb[(size_t)r * Lq + col + 1] = acc[mf][nf][rr * 2 + 1] * scale;
            }
        }
    }
}

// ==========================================================================
// softmax_k: causal softmax per row, in place (S -> P). P rounded to tf32,
// masked region zeroed so PV can run unmasked.
// ==========================================================================
__global__ void softmax_k() {
    const int r    = blockIdx.x * 8 + (threadIdx.x >> 5);
    const int lane = threadIdx.x & 31;
    const int bh = r >> 9, i = r & 511;
    float* row = g_s + (size_t)bh * Lq * Lq + (size_t)i * Lq;

    float v[16];
    float mx = -1e30f;
#pragma unroll
    for (int w = 0; w < 16; w++) {
        const int j = lane + w * 32;
        const float t = row[j];
        v[w] = (j <= i) ? t : -1e30f;
        mx = fmaxf(mx, v[w]);
    }
#pragma unroll
    for (int o = 16; o > 0; o >>= 1) mx = fmaxf(mx, __shfl_xor_sync(0xffffffffu, mx, o));
    float sum = 0.f;
#pragma unroll
    for (int w = 0; w < 16; w++) {
        v[w] = __expf(v[w] - mx);   // masked lanes underflow to 0
        sum += v[w];
    }
#pragma unroll
    for (int o = 16; o > 0; o >>= 1) sum += __shfl_xor_sync(0xffffffffu, sum, o);
    const float inv = 1.f / sum;
#pragma unroll
    for (int w = 0; w < 16; w++) {
        const int j = lane + w * 32;
        row[j] = tf32f(v[w] * inv);
    }
}

// ==========================================================================
// pv_k: O[bh] = P[bh] @ V[bh]. M=512, N=128, K truncated to m0+128 (causal).
// Output written to g_ao in [b, l, h, hd] layout, tf32-rounded.
// ==========================================================================
__global__ __launch_bounds__(256) void pv_k() {
    const int bh = blockIdx.z;
    const int m0 = blockIdx.y * 128;

    __shared__ float As[2][128 * 20];
    __shared__ float Bs[2][16 * 136];

    const float* A  = g_s + (size_t)bh * Lq * Lq;     // [512,512] row-major
    const float* Bm = g_v + (size_t)bh * Lq * HDq;    // [512,128] row-major (A@B form)

    const int tid  = threadIdx.x;
    const int lane = tid & 31, warp = tid >> 5;
    const int wm = warp >> 1, wn = warp & 1;
    const int lr = lane >> 2, lc = lane & 3;
    // A loader (lda = 512)
    const int ar0 = tid >> 2, ac0 = (tid & 3) * 4;
    const int ar1 = ar0 + 64;
    // B loader: tile 16(k) x 128(n): 512 float4, 2/thread
    const int bk0 = tid >> 5,       bc0 = (tid & 31) * 4;
    const int bk1 = (tid + 256) >> 5;  // bk0 + 8

    float acc[2][8][4];
#pragma unroll
    for (int i = 0; i < 2; i++)
#pragma unroll
        for (int j = 0; j < 8; j++)
#pragma unroll
            for (int t = 0; t < 4; t++) acc[i][j][t] = 0.f;

    const int nkt = (m0 + 128) >> 4;  // causal: P cols beyond m0+127 are zero

    {
        const float* ga = A + (size_t)m0 * Lq;
        cp_async16(&As[0][ar0 * 20 + ac0], ga + (size_t)ar0 * Lq + ac0);
        cp_async16(&As[0][ar1 * 20 + ac0], ga + (size_t)ar1 * Lq + ac0);
        cp_async16(&Bs[0][bk0 * 136 + bc0], Bm + (size_t)bk0 * HDq + bc0);
        cp_async16(&Bs[0][bk1 * 136 + bc0], Bm + (size_t)bk1 * HDq + bc0);
        CP_COMMIT;
    }

    int buf = 0;
    for (int kt = 0; kt < nkt; ++kt) {
        CP_WAIT0;
        __syncthreads();
        if (kt + 1 < nkt) {
            const int kb = (kt + 1) * 16;
            const float* ga = A + (size_t)m0 * Lq + kb;
            const int nb = buf ^ 1;
            cp_async16(&As[nb][ar0 * 20 + ac0], ga + (size_t)ar0 * Lq + ac0);
            cp_async16(&As[nb][ar1 * 20 + ac0], ga + (size_t)ar1 * Lq + ac0);
            cp_async16(&Bs[nb][bk0 * 136 + bc0], Bm + (size_t)(kb + bk0) * HDq + bc0);
            cp_async16(&Bs[nb][bk1 * 136 + bc0], Bm + (size_t)(kb + bk1) * HDq + bc0);
            CP_COMMIT;
        }
        const uint32_t* as = (const uint32_t*)As[buf];
        const uint32_t* bs = (const uint32_t*)Bs[buf];
#pragma unroll
        for (int kk = 0; kk < 16; kk += 8) {
            uint32_t af[2][4], bf[8][2];
#pragma unroll
            for (int mf = 0; mf < 2; mf++) {
                const int r = wm * 32 + mf * 16 + lr;
                af[mf][0] = as[r * 20 + kk + lc];
                af[mf][1] = as[(r + 8) * 20 + kk + lc];
                af[mf][2] = as[r * 20 + kk + lc + 4];
                af[mf][3] = as[(r + 8) * 20 + kk + lc + 4];
            }
#pragma unroll
            for (int nf = 0; nf < 8; nf++) {
                const int c = wn * 64 + nf * 8 + lr;
                bf[nf][0] = bs[(kk + lc) * 136 + c];
                bf[nf][1] = bs[(kk + lc + 4) * 136 + c];
            }
#pragma unroll
            for (int mf = 0; mf < 2; mf++)
#pragma unroll
                for (int nf = 0; nf < 8; nf++) mma_tf32(acc[mf][nf], af[mf], bf[nf]);
        }
        buf ^= 1;
    }

    const int b = bh >> 5, h = bh & 31;
#pragma unroll
    for (int mf = 0; mf < 2; mf++) {
#pragma unroll
        for (int nf = 0; nf < 8; nf++) {
            const int row = m0 + wm * 32 + mf * 16 + lr;
            const int col = wn * 64 + nf * 8 + lc * 2;  // hd
#pragma unroll
            for (int rr = 0; rr < 2; rr++) {
                const int r = row + rr * 8;
                const size_t idx = (((size_t)b * Lq + r) * Hq + h) * HDq + col;
                g_ao[idx]     = tf32f(acc[mf][nf][rr * 2 + 0]);
                g_ao[idx + 1] = tf32f(acc[mf][nf][rr * 2 + 1]);
            }
        }
    }
}

// ==========================================================================
extern "C" void kernel_launch(void* const* d_in, const int* in_sizes, int n_in,
                              void* d_out, int out_size) {
    const float* x  = (const float*)d_in[0];
    const float* Wq = (const float*)d_in[1];
    const float* bq = (const float*)d_in[2];
    const float* Wk = (const float*)d_in[3];
    const float* bk = (const float*)d_in[4];
    const float* Wv = (const float*)d_in[5];
    const float* bv = (const float*)d_in[6];
    const float* Wo = (const float*)d_in[7];
    const float* bo = (const float*)d_in[8];
    float* out = (float*)d_out;

    // 1) tf32-round inputs once (unbiased RNA rounding; mma then sees exact tf32)
    roundcpy_k<<<4096, 256>>>((const float4*)x,  0, (long)BLq * Dq / 4);
    roundcpy_k<<<2048, 256>>>((const float4*)Wq, 1, (long)Dq * Dq / 4);
    roundcpy_k<<<2048, 256>>>((const float4*)Wk, 2, (long)Dq * Dq / 4);
    roundcpy_k<<<2048, 256>>>((const float4*)Wv, 3, (long)Dq * Dq / 4);
    roundcpy_k<<<2048, 256>>>((const float4*)Wo, 4, (long)Dq * Dq / 4);

    // 2) Q/K/V projections
    dim3 gl(32, 128, 1);
    linear_k<<<gl, 256>>>(bq, nullptr, 0);
    linear_k<<<gl, 256>>>(bk, nullptr, 1);
    linear_k<<<gl, 256>>>(bv, nullptr, 2);

    // 3) scores = QK^T / sqrt(hd)  (skip fully-masked tiles)
    scores_k<<<dim3(4, 4, BHq), 256>>>();

    // 4) causal softmax in place
    softmax_k<<<(BHq * Lq) / 8, 256>>>();

    // 5) O = P @ V  (causally truncated K loop)
    pv_k<<<dim3(1, 4, BHq), 256>>>();

    // 6) output projection
    linear_k<<<gl, 256>>>(bo, out, 3);
}

// round 3
// speedup vs baseline: 4.0006x; 4.0006x over previous
#include <cuda_runtime.h>
#include <cuda_fp16.h>
#include <cstdint>

// ---------------- feature detection (per compilation target) ----------------
#if defined(__CUDA_ARCH__) && defined(__CUDA_ARCH_HAS_FEATURE__)
#  if __CUDA_ARCH_HAS_FEATURE__(SM103_ALL)
#    define HAS_TCG 1
#  endif
#endif
#ifndef HAS_TCG
#  if defined(__CUDA_ARCH__) && defined(__CUDA_ARCH_SPECIFIC__)
#    define HAS_TCG 1
#  endif
#endif
#ifndef HAS_TCG
#  define HAS_TCG 0
#endif

// ---------------- problem constants ----------------
#define Bq  32
#define Lq  512
#define Dq  4096
#define Hq  32
#define HDq 128
#define BLq (Bq*Lq)     // 16384
#define BHq (Bq*Hq)     // 1024

// tcgen05 GEMM tiling
#define TM   128
#define TN   256
#define TK   32
#define NST  4
#define A_TILE_BYTES (TM*TK*4)
#define B_TILE_BYTES (TN*TK*4)
#define STAGE_BYTES  (A_TILE_BYTES + B_TILE_BYTES)
#define NKT  (Dq/TK)     // 128
#define GEMM_SMEM (2048 + NST*STAGE_BYTES)   // 198656
#define IDESC_TF32 0x8400910u                // f32 accum, tf32 a/b, N=256, M=128

// fp16 fallback tiling
#define SST (128*40)     // smem halves per stage per operand

// ---------------- scratch (device globals; no allocations) ----------------
__device__ int    g_use_tcg;
// fp16 path
__device__ __half g_Ah [(size_t)BLq*Dq];
__device__ __half g_Wh [4][(size_t)Dq*Dq];
__device__ __half g_AOh[(size_t)BLq*Dq];
// shared by both paths
__device__ __half g_qh [(size_t)BHq*Lq*HDq];   // [b,h,l,hd]
__device__ __half g_kh [(size_t)BHq*Lq*HDq];
__device__ __half g_vh [(size_t)BHq*Lq*HDq];
__device__ __half g_vt [(size_t)BHq*Lq*HDq];   // [b,h,hd,l]
__device__ __half g_p  [(size_t)BHq*Lq*Lq];    // probs (fp16)
__device__ float  g_s  [(size_t)BHq*Lq*Lq];    // scores (fp32)
// tcgen05 path
__device__ float  g_A [(size_t)BLq*Dq];        // tf32 tiled+swizzled x
__device__ float  g_Wt[4][(size_t)Dq*Dq];      // tf32 tiled+swizzled weights
__device__ float  g_AO[(size_t)BLq*Dq];        // tf32 tiled+swizzled attn out

// ---------------- helpers ----------------
__device__ __forceinline__ float tf32f(float x) {
    uint32_t u;
    asm("cvt.rna.tf32.f32 %0, %1;" : "=r"(u) : "f"(x));
    return __uint_as_float(u);
}
__device__ __forceinline__ uint32_t swz(uint32_t off) { return off ^ ((off >> 3) & 0x70); }
__device__ __forceinline__ uint32_t smem_u32(const void* p) {
    uint32_t a;
    asm("{ .reg .u64 t; cvta.to.shared.u64 t, %1; cvt.u32.u64 %0, t; }" : "=r"(a) : "l"(p));
    return a;
}
__device__ __forceinline__ void cp_async16(void* smem, const void* gmem) {
    uint32_t s = (uint32_t)__cvta_generic_to_shared(smem);
    asm volatile("cp.async.cg.shared.global [%0], [%1], 16;\n" :: "r"(s), "l"(gmem));
}
#define CP_COMMIT asm volatile("cp.async.commit_group;\n" ::: "memory")
#define CP_WAIT0  asm volatile("cp.async.wait_group 0;\n" ::: "memory")

__device__ __forceinline__ void mma_f16(float* c, const uint32_t* a, const uint32_t* b) {
    asm volatile(
        "mma.sync.aligned.m16n8k16.row.col.f32.f16.f16.f32 "
        "{%0,%1,%2,%3},{%4,%5,%6,%7},{%8,%9},{%0,%1,%2,%3};"
        : "+f"(c[0]), "+f"(c[1]), "+f"(c[2]), "+f"(c[3])
        : "r"(a[0]), "r"(a[1]), "r"(a[2]), "r"(a[3]), "r"(b[0]), "r"(b[1]));
}

__device__ __forceinline__ int tcg_active() { return *(volatile int*)&g_use_tcg; }

// ==========================================================================
// probe: records whether the RUNNING SASS has tcgen05 support
// ==========================================================================
__global__ void probe_k() {
#if HAS_TCG
    g_use_tcg = 1;
#else
    g_use_tcg = 0;
#endif
}

// ==========================================================================
// fp16 prepass: fp32 -> fp16 (round-to-nearest)
// ==========================================================================
__global__ void prep_h(const float4* __restrict__ src, int sel, long n4) {
    if (tcg_active()) return;
    __half2* dst = (__half2*)(sel == 0 ? g_Ah : g_Wh[sel - 1]);
    for (long i = (long)blockIdx.x * blockDim.x + threadIdx.x; i < n4;
         i += (long)gridDim.x * blockDim.x) {
        float4 t = src[i];
        dst[2 * i]     = __floats2half2_rn(t.x, t.y);
        dst[2 * i + 1] = __floats2half2_rn(t.z, t.w);
    }
}

// ==========================================================================
// tcgen05 prepass: tf32-round + tile(128x32 / 256x32) + SW128 swizzle
// ==========================================================================
__global__ void prep_x(const float4* __restrict__ src) {
    if (!tcg_active()) return;
    const long n4 = (long)BLq * Dq / 4;
    for (long i4 = (long)blockIdx.x * blockDim.x + threadIdx.x; i4 < n4;
         i4 += (long)gridDim.x * blockDim.x) {
        long i = i4 * 4;
        int m = (int)(i >> 12), k = (int)(i & 4095);
        int mb = m >> 7, r = m & 127, kt = k >> 5, c = k & 31;
        float4 t = src[i4];
        t.x = tf32f(t.x); t.y = tf32f(t.y); t.z = tf32f(t.z); t.w = tf32f(t.w);
        size_t base = ((size_t)(mb * NKT + kt)) * (TM * TK);
        uint32_t off = swz((uint32_t)(r * 128 + c * 4));
        *reinterpret_cast<float4*>((char*)g_A + base * 4 + off) = t;
    }
}
__global__ void prep_w(const float4* __restrict__ src, int which) {
    if (!tcg_active()) return;
    const long n4 = (long)Dq * Dq / 4;
    for (long i4 = (long)blockIdx.x * blockDim.x + threadIdx.x; i4 < n4;
         i4 += (long)gridDim.x * blockDim.x) {
        long i = i4 * 4;
        int n = (int)(i >> 12), k = (int)(i & 4095);
        int nb = n >> 8, r = n & 255, kt = k >> 5, c = k & 31;
        float4 t = src[i4];
        t.x = tf32f(t.x); t.y = tf32f(t.y); t.z = tf32f(t.z); t.w = tf32f(t.w);
        size_t base = ((size_t)(nb * NKT + kt)) * (TN * TK);
        uint32_t off = swz((uint32_t)(r * 128 + c * 4));
        *reinterpret_cast<float4*>((char*)g_Wt[which] + base * 4 + off) = t;
    }
}

// ==========================================================================
// tcgen05 tf32 GEMM (guarded). C[16384,4096] = A @ W^T + bias.
// ==========================================================================
#if HAS_TCG
#define MBARRIER_INIT(a, n) \
    asm volatile("mbarrier.init.shared.b64 [%0], %1;" :: "r"((uint32_t)(a)), "r"((uint32_t)(n)) : "memory")
#define MBARRIER_EXPECT_TX(a, b) \
    asm volatile("mbarrier.arrive.expect_tx.shared.b64 _, [%0], %1;" :: "r"((uint32_t)(a)), "r"((uint32_t)(b)) : "memory")
#define MBARRIER_WAIT_PARITY(a, ph) do { \
    asm volatile("{\n\t.reg .pred P1;\n\t" \
        "WAIT_LOOP_%=:\n\t" \
        "mbarrier.try_wait.parity.acquire.cta.shared::cta.b64 P1, [%0], %1, 0x989680;\n\t" \
        "@P1 bra.uni WAIT_DONE_%=;\n\t" \
        "bra.uni WAIT_LOOP_%=;\n\t" \
        "WAIT_DONE_%=:\n\t}" \
        :: "r"((uint32_t)(a)), "r"((uint32_t)(ph)) : "memory"); \
} while (0)
#define TCGEN05_ALLOC(sa, n) \
    asm volatile("tcgen05.alloc.cta_group::1.sync.aligned.shared::cta.b32 [%0], %1;" \
        :: "r"((uint32_t)(sa)), "r"((uint32_t)(n)) : "memory")
#define TCGEN05_DEALLOC(t, n) \
    asm volatile("tcgen05.dealloc.cta_group::1.sync.aligned.b32 %0, %1;" :: "r"(t), "r"((uint32_t)(n)))
#define TCGEN05_RELINQ() \
    asm volatile("tcgen05.relinquish_alloc_permit.cta_group::1.sync.aligned;")
#define TCGEN05_COMMIT(mb) \
    asm volatile("tcgen05.commit.cta_group::1.mbarrier::arrive::one.shared::cluster.b64 [%0];" \
        :: "r"((uint32_t)(mb)) : "memory")
#define TCGEN05_FENCE_AFTER() asm volatile("tcgen05.fence::after_thread_sync;" ::: "memory")
#define TCGEN05_WAIT_LD()     asm volatile("tcgen05.wait::ld.sync.aligned;" ::: "memory")
#define TCGEN05_LD_X32(r, ta) \
    asm volatile("tcgen05.ld.sync.aligned.32x32b.x32.b32 " \
        "{%0,%1,%2,%3,%4,%5,%6,%7,%8,%9,%10,%11,%12,%13,%14,%15," \
        "%16,%17,%18,%19,%20,%21,%22,%23,%24,%25,%26,%27,%28,%29,%30,%31}, [%32];" \
        : "=r"((r)[0]),"=r"((r)[1]),"=r"((r)[2]),"=r"((r)[3]),"=r"((r)[4]),"=r"((r)[5]),"=r"((r)[6]),"=r"((r)[7]), \
          "=r"((r)[8]),"=r"((r)[9]),"=r"((r)[10]),"=r"((r)[11]),"=r"((r)[12]),"=r"((r)[13]),"=r"((r)[14]),"=r"((r)[15]), \
          "=r"((r)[16]),"=r"((r)[17]),"=r"((r)[18]),"=r"((r)[19]),"=r"((r)[20]),"=r"((r)[21]),"=r"((r)[22]),"=r"((r)[23]), \
          "=r"((r)[24]),"=r"((r)[25]),"=r"((r)[26]),"=r"((r)[27]),"=r"((r)[28]),"=r"((r)[29]),"=r"((r)[30]),"=r"((r)[31]) \
        : "r"(ta))

__device__ __forceinline__ uint32_t elect_one_pred() {
    uint32_t p;
    asm volatile("{ .reg .pred p; elect.sync _|p, 0xFFFFFFFF; selp.b32 %0, 1, 0, p; }" : "=r"(p));
    return p;
}
__device__ __forceinline__ uint64_t mk_desc(uint32_t addr) {
    const uint64_t base = (uint64_t(2) << 61) | (uint64_t(1) << 46) | (uint64_t(64) << 32) | (uint64_t(1) << 16);
    return base | ((uint64_t)(addr >> 4) & 0x3FFF);
}
__device__ __forceinline__ void mma_tf32_ss(uint32_t d, uint64_t ad, uint64_t bd,
                                            uint32_t idesc, uint32_t en) {
    asm volatile(
        "{\n\t.reg .pred p;\n\tsetp.ne.u32 p, %4, 0;\n\t"
        "tcgen05.mma.cta_group::1.kind::tf32 [%0], %1, %2, %3, {%5,%5,%5,%5}, p;\n\t}"
        :: "r"(d), "l"(ad), "l"(bd), "r"(idesc), "r"(en), "r"(0u) : "memory");
}
__device__ __forceinline__ void bulk_g2s(uint32_t dst, const void* src, uint32_t bytes, uint32_t mbar) {
    asm volatile(
        "cp.async.bulk.shared::cluster.global.mbarrier::complete_tx::bytes [%0], [%1], %2, [%3];"
        :: "r"(dst), "l"(src), "r"(bytes), "r"(mbar) : "memory");
}
#endif  // HAS_TCG

__global__ __launch_bounds__(128, 1) void gemm_tc(const float* __restrict__ bias,
                                                  float* __restrict__ outp, int which) {
    if (!tcg_active()) return;
#if HAS_TCG
    extern __shared__ char smem[];
    const uint32_t sbase = smem_u32(smem);
    const uint32_t mb0   = sbase + 8;
    const uint32_t done  = sbase + 8 + 16 * NST;
    const uint32_t stg0  = (sbase + 128 + 1023) & ~1023u;

    const int tid = threadIdx.x, wid = tid >> 5, lane = tid & 31;
    const int m0 = blockIdx.y * TM, n0 = blockIdx.x * TN;

    if (wid == 0) TCGEN05_ALLOC(sbase, 256);
    if (tid == 0) {
#pragma unroll
        for (int s = 0; s < NST; s++) {
            MBARRIER_INIT(mb0 + 16 * s, 1);
            MBARRIER_INIT(mb0 + 16 * s + 8, 1);
        }
        MBARRIER_INIT(done, 1);
    }
    __syncthreads();

    uint32_t tmem;
    asm volatile("ld.shared.b32 %0, [%1];" : "=r"(tmem) : "r"(sbase));

    const char* Atiles = (const char*)(which < 3 ? g_A : g_AO)
                         + (size_t)blockIdx.y * NKT * A_TILE_BYTES;
    const char* Btiles = (const char*)g_Wt[which]
                         + (size_t)blockIdx.x * NKT * B_TILE_BYTES;

    if (tid == 96) {
        int s = 0, ph = 1;
        for (int kt = 0; kt < NKT; ++kt) {
            MBARRIER_WAIT_PARITY(mb0 + 16 * s + 8, ph);
            MBARRIER_EXPECT_TX(mb0 + 16 * s, STAGE_BYTES);
            bulk_g2s(stg0 + s * STAGE_BYTES,
                     Atiles + (size_t)kt * A_TILE_BYTES, A_TILE_BYTES, mb0 + 16 * s);
            bulk_g2s(stg0 + s * STAGE_BYTES + A_TILE_BYTES,
                     Btiles + (size_t)kt * B_TILE_BYTES, B_TILE_BYTES, mb0 + 16 * s);
            if (++s == NST) { s = 0; ph ^= 1; }
        }
    } else if (wid == 0) {
        if (elect_one_pred()) {
            int s = 0, ph = 0;
            uint32_t en = 0;
            for (int kt = 0; kt < NKT; ++kt) {
                MBARRIER_WAIT_PARITY(mb0 + 16 * s, ph);
                const uint64_t ad = mk_desc(stg0 + s * STAGE_BYTES);
                const uint64_t bd = mk_desc(stg0 + s * STAGE_BYTES + A_TILE_BYTES);
#pragma unroll
                for (int c = 0; c < 4; c++) {
                    mma_tf32_ss(tmem, ad + 2 * c, bd + 2 * c, IDESC_TF32, en);
                    en = 1;
                }
                TCGEN05_COMMIT(mb0 + 16 * s + 8);
                if (++s == NST) { s = 0; ph ^= 1; }
            }
            TCGEN05_COMMIT(done);
        }
    }

    MBARRIER_WAIT_PARITY(done, 0);
    TCGEN05_FENCE_AFTER();

    const int m = m0 + wid * 32 + lane;
    const int b = m >> 9, l = m & 511;
#pragma unroll
    for (int ch = 0; ch < 8; ch++) {
        uint32_t r[32];
        TCGEN05_LD_X32(r, tmem + ch * 32);
        TCGEN05_WAIT_LD();
        const int cb = n0 + ch * 32;
        if (which < 3) {
            __half* dst = (which == 0) ? g_qh : (which == 1) ? g_kh : g_vh;
            const int h = cb >> 7;
            const size_t rowbase = (((size_t)b * Hq + h) * Lq + l) * HDq;
#pragma unroll
            for (int j = 0; j < 32; j += 2) {
                const int col = cb + j;
                __half2 hv = __floats2half2_rn(__uint_as_float(r[j]) + bias[col],
                                               __uint_as_float(r[j + 1]) + bias[col + 1]);
                *reinterpret_cast<__half2*>(&dst[rowbase + (col & 127)]) = hv;
            }
        } else {
#pragma unroll
            for (int j = 0; j < 32; j += 2) {
                const int col = cb + j;
                float2 v;
                v.x = __uint_as_float(r[j])     + bias[col];
                v.y = __uint_as_float(r[j + 1]) + bias[col + 1];
                *reinterpret_cast<float2*>(&outp[(size_t)m * Dq + col]) = v;
            }
        }
    }

    __syncthreads();
    if (wid == 0) {
        TCGEN05_RELINQ();
        TCGEN05_DEALLOC(tmem, 256);
    }
#endif  // HAS_TCG
}

// ==========================================================================
// fp16 block GEMM core: 128x128 tile, kstep=32, 256 threads (8 warps 4x2),
// double-buffered cp.async. A row-major [m][k], B row-major [n][k].
// ==========================================================================
__device__ __forceinline__ void gemm16_tile(const __half* __restrict__ Ag, int lda,
                                            const __half* __restrict__ Bg, int ldb,
                                            int nkt, float (&acc)[2][8][4],
                                            __half* As, __half* Bs) {
    const int tid = threadIdx.x, lane = tid & 31, warp = tid >> 5;
    const int wm = warp >> 1, wn = warp & 1;
    const int lr = lane >> 2, lc = lane & 3;
    const int r0 = tid >> 2, c0 = (tid & 3) * 8, r1 = r0 + 64;

    cp_async16(&As[r0 * 40 + c0], Ag + (size_t)r0 * lda + c0);
    cp_async16(&As[r1 * 40 + c0], Ag + (size_t)r1 * lda + c0);
    cp_async16(&Bs[r0 * 40 + c0], Bg + (size_t)r0 * ldb + c0);
    cp_async16(&Bs[r1 * 40 + c0], Bg + (size_t)r1 * ldb + c0);
    CP_COMMIT;

    int buf = 0;
    for (int kt = 0; kt < nkt; ++kt) {
        CP_WAIT0;
        __syncthreads();
        if (kt + 1 < nkt) {
            const int k0 = (kt + 1) * 32;
            const int nb = buf ^ 1;
            cp_async16(&As[nb * SST + r0 * 40 + c0], Ag + (size_t)r0 * lda + k0 + c0);
            cp_async16(&As[nb * SST + r1 * 40 + c0], Ag + (size_t)r1 * lda + k0 + c0);
            cp_async16(&Bs[nb * SST + r0 * 40 + c0], Bg + (size_t)r0 * ldb + k0 + c0);
            cp_async16(&Bs[nb * SST + r1 * 40 + c0], Bg + (size_t)r1 * ldb + k0 + c0);
            CP_COMMIT;
        }
        const uint32_t* as = (const uint32_t*)(As + buf * SST);
        const uint32_t* bs = (const uint32_t*)(Bs + buf * SST);
#pragma unroll
        for (int kk2 = 0; kk2 < 2; kk2++) {
            const int kc = kk2 * 8 + lc;
            uint32_t af[2][4], bf[8][2];
#pragma unroll
            for (int mf = 0; mf < 2; mf++) {
                const int R = (wm * 32 + mf * 16 + lr) * 20;
                af[mf][0] = as[R + kc];
                af[mf][1] = as[R + 160 + kc];
                af[mf][2] = as[R + kc + 4];
                af[mf][3] = as[R + 160 + kc + 4];
            }
#pragma unroll
            for (int nf = 0; nf < 8; nf++) {
                const int C = (wn * 64 + nf * 8 + lr) * 20;
                bf[nf][0] = bs[C + kc];
                bf[nf][1] = bs[C + kc + 4];
            }
#pragma unroll
            for (int mf = 0; mf < 2; mf++)
#pragma unroll
                for (int nf = 0; nf < 8; nf++) mma_f16(acc[mf][nf], af[mf], bf[nf]);
        }
        buf ^= 1;
    }
}

#define DECL_ACC(acc) \
    float acc[2][8][4]; \
    _Pragma("unroll") for (int i_ = 0; i_ < 2; i_++) \
    _Pragma("unroll") for (int j_ = 0; j_ < 8; j_++) \
    _Pragma("unroll") for (int t_ = 0; t_ < 4; t_++) acc[i_][j_][t_] = 0.f;

// ==========================================================================
// fp16 linear: C[16384,4096] = A @ W^T + bias. which 0/1/2 -> q/k/v halves,
// which 3 -> fp32 out.
// ==========================================================================
__global__ __launch_bounds__(256) void lin16_k(const float* __restrict__ bias,
                                               float* __restrict__ outp, int which) {
    if (tcg_active()) return;
    __shared__ __half As[2 * SST];
    __shared__ __half Bs[2 * SST];

    const __half* A = (which < 3) ? g_Ah : g_AOh;
    const __half* W = g_Wh[which];
    const int m0 = blockIdx.y * 128, n0 = blockIdx.x * 128;

    DECL_ACC(acc);
    gemm16_tile(A + (size_t)m0 * Dq, Dq, W + (size_t)n0 * Dq, Dq, Dq / 32, acc, As, Bs);

    const int tid = threadIdx.x, lane = tid & 31, warp = tid >> 5;
    const int wm = warp >> 1, wn = warp & 1, lr = lane >> 2, lc = lane & 3;
#pragma unroll
    for (int mf = 0; mf < 2; mf++) {
#pragma unroll
        for (int nf = 0; nf < 8; nf++) {
            const int col = n0 + wn * 64 + nf * 8 + lc * 2;
            const float b0 = bias[col], b1 = bias[col + 1];
#pragma unroll
            for (int rr = 0; rr < 2; rr++) {
                const int m = m0 + wm * 32 + mf * 16 + lr + rr * 8;
                const float v0 = acc[mf][nf][rr * 2]     + b0;
                const float v1 = acc[mf][nf][rr * 2 + 1] + b1;
                if (which < 3) {
                    __half* dst = (which == 0) ? g_qh : (which == 1) ? g_kh : g_vh;
                    const int b = m >> 9, l = m & 511;
                    const int h = col >> 7, hd = col & 127;
                    *reinterpret_cast<__half2*>(
                        &dst[(((size_t)b * Hq + h) * Lq + l) * HDq + hd]) =
                        __floats2half2_rn(v0, v1);
                } else {
                    float2 v; v.x = v0; v.y = v1;
                    *reinterpret_cast<float2*>(&outp[(size_t)m * Dq + col]) = v;
                }
            }
        }
    }
}

// ==========================================================================
// V transpose: [b,h,l,hd] -> [b,h,hd,l] (both paths)
// ==========================================================================
__global__ void vt_k() {
    __shared__ __half t[32][33];
    const int bh = blockIdx.z;
    const int l0 = blockIdx.x * 32, d0 = blockIdx.y * 32;
    const int tx = threadIdx.x, ty = threadIdx.y;
    const __half* src = g_vh + (size_t)bh * Lq * HDq;
    __half* dst = g_vt + (size_t)bh * HDq * Lq;
#pragma unroll
    for (int j = 0; j < 4; j++) {
        const int l = l0 + ty + j * 8;
        t[ty + j * 8][tx] = src[(size_t)l * HDq + d0 + tx];
    }
    __syncthreads();
#pragma unroll
    for (int j = 0; j < 4; j++) {
        const int d = d0 + ty + j * 8;
        dst[(size_t)d * Lq + l0 + tx] = t[tx][ty + j * 8];
    }
}

// ==========================================================================
// scores (fp16 mma): S = QK^T/sqrt(hd), fp32 out; causal tile skip
// ==========================================================================
__global__ __launch_bounds__(256) void scores16_k() {
    const int bh = blockIdx.z;
    const int m0 = blockIdx.y * 128, n0 = blockIdx.x * 128;
    if (n0 > m0 + 127) return;

    __shared__ __half As[2 * SST];
    __shared__ __half Bs[2 * SST];

    DECL_ACC(acc);
    gemm16_tile(g_qh + ((size_t)bh * Lq + m0) * HDq, HDq,
                g_kh + ((size_t)bh * Lq + n0) * HDq, HDq, HDq / 32, acc, As, Bs);

    const int tid = threadIdx.x, lane = tid & 31, warp = tid >> 5;
    const int wm = warp >> 1, wn = warp & 1, lr = lane >> 2, lc = lane & 3;
    const float scale = 0.0883883476483184405501f;
    float* Sb = g_s + (size_t)bh * Lq * Lq;
#pragma unroll
    for (int mf = 0; mf < 2; mf++) {
#pragma unroll
        for (int nf = 0; nf < 8; nf++) {
            const int col = n0 + wn * 64 + nf * 8 + lc * 2;
#pragma unroll
            for (int rr = 0; rr < 2; rr++) {
                const int r = m0 + wm * 32 + mf * 16 + lr + rr * 8;
                float2 v;
                v.x = acc[mf][nf][rr * 2]     * scale;
                v.y = acc[mf][nf][rr * 2 + 1] * scale;
                *reinterpret_cast<float2*>(&Sb[(size_t)r * Lq + col]) = v;
            }
        }
    }
}

// ==========================================================================
// causal softmax: fp32 S row -> fp16 P row (masked cols -> 0)
// ==========================================================================
__global__ void softmax_k() {
    const int r    = blockIdx.x * 8 + (threadIdx.x >> 5);
    const int lane = threadIdx.x & 31;
    const int bh = r >> 9, i = r & 511;
    const float* row = g_s + (size_t)bh * Lq * Lq + (size_t)i * Lq;
    __half* prow = g_p + (size_t)bh * Lq * Lq + (size_t)i * Lq;

    float v[16];
    float mx = -1e30f;
#pragma unroll
    for (int w = 0; w < 16; w++) {
        const int j = lane + w * 32;
        const float t = row[j];
        v[w] = (j <= i) ? t : -1e30f;
        mx = fmaxf(mx, v[w]);
    }
#pragma unroll
    for (int o = 16; o > 0; o >>= 1) mx = fmaxf(mx, __shfl_xor_sync(0xffffffffu, mx, o));
    float sum = 0.f;
#pragma unroll
    for (int w = 0; w < 16; w++) {
        v[w] = __expf(v[w] - mx);
        sum += v[w];
    }
#pragma unroll
    for (int o = 16; o > 0; o >>= 1) sum += __shfl_xor_sync(0xffffffffu, sum, o);
    const float inv = 1.f / sum;
#pragma unroll
    for (int w = 0; w < 16; w++) {
        prow[lane + w * 32] = __float2half_rn(v[w] * inv);
    }
}

// ==========================================================================
// pv (fp16 mma): O = P @ V (via V^T as B). Writes g_AOh (fp16 row-major)
// and g_AO (tf32 tiled+swizzled for tcg final GEMM).
// ==========================================================================
__global__ __launch_bounds__(256) void pv16_k() {
    const int bh = blockIdx.z;
    const int m0 = blockIdx.y * 128;

    __shared__ __half As[2 * SST];
    __shared__ __half Bs[2 * SST];

    DECL_ACC(acc);
    gemm16_tile(g_p + (size_t)bh * Lq * Lq + (size_t)m0 * Lq, Lq,
                g_vt + (size_t)bh * HDq * Lq, Lq, (m0 + 128) / 32, acc, As, Bs);

    const int tid = threadIdx.x, lane = tid & 31, warp = tid >> 5;
    const int wm = warp >> 1, wn = warp & 1, lr = lane >> 2, lc = lane & 3;
    const int b = bh >> 5, h = bh & 31;
#pragma unroll
    for (int mf = 0; mf < 2; mf++) {
#pragma unroll
        for (int nf = 0; nf < 8; nf++) {
            const int col = wn * 64 + nf * 8 + lc * 2;   // hd
#pragma unroll
            for (int rr = 0; rr < 2; rr++) {
                const int r = m0 + wm * 32 + mf * 16 + lr + rr * 8;  // l
                const float v0 = acc[mf][nf][rr * 2];
                const float v1 = acc[mf][nf][rr * 2 + 1];
                const int R = b * Lq + r;
                const int C = h * HDq + col;
                // fp16 row-major (fallback final GEMM input)
                *reinterpret_cast<__half2*>(&g_AOh[(size_t)R * Dq + C]) =
                    __floats2half2_rn(v0, v1);
                // tf32 tiled+swizzled (tcg final GEMM input)
                const int mb = R >> 7, rl = R & 127, kt2 = C >> 5, cc = C & 31;
                char* tb = (char*)g_AO + ((size_t)(mb * NKT + kt2)) * (TM * TK) * 4;
                *reinterpret_cast<float*>(tb + swz((uint32_t)(rl * 128 + cc * 4))) = tf32f(v0);
                *reinterpret_cast<float*>(tb + swz((uint32_t)(rl * 128 + (cc + 1) * 4))) = tf32f(v1);
            }
        }
    }
}

// ==========================================================================
extern "C" void kernel_launch(void* const* d_in, const int* in_sizes, int n_in,
                              void* d_out, int out_size) {
    const float* x  = (const float*)d_in[0];
    const float* Wq = (const float*)d_in[1];
    const float* bq = (const float*)d_in[2];
    const float* Wk = (const float*)d_in[3];
    const float* bk = (const float*)d_in[4];
    const float* Wv = (const float*)d_in[5];
    const float* bv = (const float*)d_in[6];
    const float* Wo = (const float*)d_in[7];
    const float* bo = (const float*)d_in[8];
    float* out = (float*)d_out;

    cudaFuncSetAttribute(gemm_tc, cudaFuncAttributeMaxDynamicSharedMemorySize, GEMM_SMEM);

    // 0) feature probe (device-side dispatch flag)
    probe_k<<<1, 1>>>();

    // 1) prepasses (each self-gated on the flag)
    prep_h<<<2048, 256>>>((const float4*)x,  0, (long)BLq * Dq / 4);
    prep_h<<<2048, 256>>>((const float4*)Wq, 1, (long)Dq * Dq / 4);
    prep_h<<<2048, 256>>>((const float4*)Wk, 2, (long)Dq * Dq / 4);
    prep_h<<<2048, 256>>>((const float4*)Wv, 3, (long)Dq * Dq / 4);
    prep_h<<<2048, 256>>>((const float4*)Wo, 4, (long)Dq * Dq / 4);
    prep_x<<<8192, 256>>>((const float4*)x);
    prep_w<<<4096, 256>>>((const float4*)Wq, 0);
    prep_w<<<4096, 256>>>((const float4*)Wk, 1);
    prep_w<<<4096, 256>>>((const float4*)Wv, 2);
    prep_w<<<4096, 256>>>((const float4*)Wo, 3);

    // 2) Q/K/V projections (exactly one variant does work)
    dim3 gl16(32, 128), gltc(Dq / TN, BLq / TM);
    lin16_k<<<gl16, 256>>>(bq, nullptr, 0);
    lin16_k<<<gl16, 256>>>(bk, nullptr, 1);
    lin16_k<<<gl16, 256>>>(bv, nullptr, 2);
    gemm_tc<<<gltc, 128, GEMM_SMEM>>>(bq, nullptr, 0);
    gemm_tc<<<gltc, 128, GEMM_SMEM>>>(bk, nullptr, 1);
    gemm_tc<<<gltc, 128, GEMM_SMEM>>>(bv, nullptr, 2);

    // 3) attention (shared by both paths)
    vt_k<<<dim3(16, 4, BHq), dim3(32, 8)>>>();
    scores16_k<<<dim3(4, 4, BHq), 256>>>();
    softmax_k<<<(BHq * Lq) / 8, 256>>>();
    pv16_k<<<dim3(1, 4, BHq), 256>>>();

    // 4) output projection
    lin16_k<<<gl16, 256>>>(bo, out, 3);
    gemm_tc<<<gltc, 128, GEMM_SMEM>>>(bo, out, 3);
}

// round 4
// speedup vs baseline: 7.4397x; 1.8596x over previous
#include <cuda_runtime.h>
#include <cuda_fp16.h>
#include <cstdint>

// ---------------- feature detection (per compilation target) ----------------
#if defined(__CUDA_ARCH__) && defined(__CUDA_ARCH_HAS_FEATURE__)
#  if __CUDA_ARCH_HAS_FEATURE__(SM103_ALL)
#    define HAS_TCG 1
#  endif
#endif
#ifndef HAS_TCG
#  if defined(__CUDA_ARCH__) && defined(__CUDA_ARCH_SPECIFIC__)
#    define HAS_TCG 1
#  endif
#endif
#ifndef HAS_TCG
#  define HAS_TCG 0
#endif

// ---------------- problem constants ----------------
#define Bq  32
#define Lq  512
#define Dq  4096
#define Hq  32
#define HDq 128
#define BLq (Bq*Lq)     // 16384
#define BHq (Bq*Hq)     // 1024

// ---------------- fp16 tcgen05 GEMM tiling ----------------
// CTA tile 256x256 = two 128x256 MMAs sharing B. K-tile = 64 halves (128B rows, SW128).
#define TKH   64
#define NKT16 (Dq/TKH)          // 64 k-tiles
#define A_TB  (128*TKH*2)       // 16384 B per A tile
#define B_TB  (256*TKH*2)       // 32768 B per B tile
#define STG_B (2*A_TB + B_TB)   // 65536 B per stage
#define NST   3
#define GEMM_SMEM (2048 + NST*STG_B)   // 198656
// idesc: f32 accum (1<<4), f16 a/b (0), N=256 ((N/8)<<17), M=128 ((M/16)<<24)
#define IDESC_F16 0x8400010u

// flash attention smem: Q + 2xK + 2xV tiles, each 128 rows x 136 halves
#define FA_TILE_H (128*136)               // 17408 halves
#define FA_SMEM   (5*FA_TILE_H*2)         // 174080 B

// ---------------- scratch (device globals; no allocations) ----------------
__device__ __half g_A16 [(size_t)BLq*Dq];     // x: fp16 tiled+swizzled A-tiles
__device__ __half g_W16 [4][(size_t)Dq*Dq];   // weights: fp16 tiled+swizzled B-tiles
__device__ __half g_AO16[(size_t)BLq*Dq];     // attn out: fp16 tiled+swizzled A-tiles
__device__ __half g_qh  [(size_t)BHq*Lq*HDq]; // [b,h,l,hd]
__device__ __half g_kh  [(size_t)BHq*Lq*HDq];
__device__ __half g_vh  [(size_t)BHq*Lq*HDq];
__device__ __half g_vt  [(size_t)BHq*Lq*HDq]; // [b,h,hd,l]

// ---------------- helpers ----------------
__device__ __forceinline__ uint32_t swz(uint32_t off) { return off ^ ((off >> 3) & 0x70); }
__device__ __forceinline__ uint32_t smem_u32(const void* p) {
    uint32_t a;
    asm("{ .reg .u64 t; cvta.to.shared.u64 t, %1; cvt.u32.u64 %0, t; }" : "=r"(a) : "l"(p));
    return a;
}
__device__ __forceinline__ void cp_async16(void* smem, const void* gmem) {
    uint32_t s = (uint32_t)__cvta_generic_to_shared(smem);
    asm volatile("cp.async.cg.shared.global [%0], [%1], 16;\n" :: "r"(s), "l"(gmem));
}
#define CP_COMMIT asm volatile("cp.async.commit_group;\n" ::: "memory")
#define CP_WAIT0  asm volatile("cp.async.wait_group 0;\n" ::: "memory")
#define CP_WAIT1  asm volatile("cp.async.wait_group 1;\n" ::: "memory")

__device__ __forceinline__ void mma_f16(float* c, const uint32_t* a, const uint32_t* b) {
    asm volatile(
        "mma.sync.aligned.m16n8k16.row.col.f32.f16.f16.f32 "
        "{%0,%1,%2,%3},{%4,%5,%6,%7},{%8,%9},{%0,%1,%2,%3};"
        : "+f"(c[0]), "+f"(c[1]), "+f"(c[2]), "+f"(c[3])
        : "r"(a[0]), "r"(a[1]), "r"(a[2]), "r"(a[3]), "r"(b[0]), "r"(b[1]));
}
__device__ __forceinline__ uint32_t h2u(float a, float b) {
    __half2 h = __floats2half2_rn(a, b);
    return *reinterpret_cast<uint32_t*>(&h);
}

// ==========================================================================
// prepass: fp32 -> fp16 + tile + SW128 swizzle. 8 floats (one 16B half-write)
// per thread.
// ==========================================================================
__global__ void prep_x16(const float4* __restrict__ src) {
    const size_t gid = (size_t)blockIdx.x * blockDim.x + threadIdx.x;
    const size_t i = gid * 8;
    const int m = (int)(i >> 12), k = (int)(i & 4095);
    const int mb = m >> 7, r = m & 127, kt = k >> 6, c = k & 63;
    float4 u = src[2 * gid], v = src[2 * gid + 1];
    uint4 o;
    o.x = h2u(u.x, u.y); o.y = h2u(u.z, u.w);
    o.z = h2u(v.x, v.y); o.w = h2u(v.z, v.w);
    char* tb = (char*)g_A16 + (size_t)(mb * NKT16 + kt) * A_TB;
    *reinterpret_cast<uint4*>(tb + swz((uint32_t)(r * 128 + c * 2))) = o;
}
__global__ void prep_w16(const float4* __restrict__ src, int which) {
    const size_t gid = (size_t)blockIdx.x * blockDim.x + threadIdx.x;
    const size_t i = gid * 8;
    const int n = (int)(i >> 12), k = (int)(i & 4095);
    const int nb = n >> 8, r = n & 255, kt = k >> 6, c = k & 63;
    float4 u = src[2 * gid], v = src[2 * gid + 1];
    uint4 o;
    o.x = h2u(u.x, u.y); o.y = h2u(u.z, u.w);
    o.z = h2u(v.x, v.y); o.w = h2u(v.z, v.w);
    char* tb = (char*)g_W16[which] + (size_t)(nb * NKT16 + kt) * B_TB;
    *reinterpret_cast<uint4*>(tb + swz((uint32_t)(r * 128 + c * 2))) = o;
}

// ==========================================================================
// tcgen05 fp16 GEMM: C[16384,4096] = A @ W^T + bias. CTA tile 256x256.
// which 0/1/2 -> q/k/v (fp16, head-split), 3 -> fp32 out.
// ==========================================================================
#if HAS_TCG
#define MBARRIER_INIT(a, n) \
    asm volatile("mbarrier.init.shared.b64 [%0], %1;" :: "r"((uint32_t)(a)), "r"((uint32_t)(n)) : "memory")
#define MBARRIER_EXPECT_TX(a, b) \
    asm volatile("mbarrier.arrive.expect_tx.shared.b64 _, [%0], %1;" :: "r"((uint32_t)(a)), "r"((uint32_t)(b)) : "memory")
#define MBARRIER_WAIT_PARITY(a, ph) do { \
    asm volatile("{\n\t.reg .pred P1;\n\t" \
        "WAIT_LOOP_%=:\n\t" \
        "mbarrier.try_wait.parity.acquire.cta.shared::cta.b64 P1, [%0], %1, 0x989680;\n\t" \
        "@P1 bra.uni WAIT_DONE_%=;\n\t" \
        "bra.uni WAIT_LOOP_%=;\n\t" \
        "WAIT_DONE_%=:\n\t}" \
        :: "r"((uint32_t)(a)), "r"((uint32_t)(ph)) : "memory"); \
} while (0)
#define TCGEN05_ALLOC(sa, n) \
    asm volatile("tcgen05.alloc.cta_group::1.sync.aligned.shared::cta.b32 [%0], %1;" \
        :: "r"((uint32_t)(sa)), "r"((uint32_t)(n)) : "memory")
#define TCGEN05_DEALLOC(t, n) \
    asm volatile("tcgen05.dealloc.cta_group::1.sync.aligned.b32 %0, %1;" :: "r"(t), "r"((uint32_t)(n)))
#define TCGEN05_RELINQ() \
    asm volatile("tcgen05.relinquish_alloc_permit.cta_group::1.sync.aligned;")
#define TCGEN05_COMMIT(mb) \
    asm volatile("tcgen05.commit.cta_group::1.mbarrier::arrive::one.shared::cluster.b64 [%0];" \
        :: "r"((uint32_t)(mb)) : "memory")
#define TCGEN05_FENCE_AFTER() asm volatile("tcgen05.fence::after_thread_sync;" ::: "memory")
#define TCGEN05_WAIT_LD()     asm volatile("tcgen05.wait::ld.sync.aligned;" ::: "memory")
#define TCGEN05_LD_X32(r, ta) \
    asm volatile("tcgen05.ld.sync.aligned.32x32b.x32.b32 " \
        "{%0,%1,%2,%3,%4,%5,%6,%7,%8,%9,%10,%11,%12,%13,%14,%15," \
        "%16,%17,%18,%19,%20,%21,%22,%23,%24,%25,%26,%27,%28,%29,%30,%31}, [%32];" \
        : "=r"((r)[0]),"=r"((r)[1]),"=r"((r)[2]),"=r"((r)[3]),"=r"((r)[4]),"=r"((r)[5]),"=r"((r)[6]),"=r"((r)[7]), \
          "=r"((r)[8]),"=r"((r)[9]),"=r"((r)[10]),"=r"((r)[11]),"=r"((r)[12]),"=r"((r)[13]),"=r"((r)[14]),"=r"((r)[15]), \
          "=r"((r)[16]),"=r"((r)[17]),"=r"((r)[18]),"=r"((r)[19]),"=r"((r)[20]),"=r"((r)[21]),"=r"((r)[22]),"=r"((r)[23]), \
          "=r"((r)[24]),"=r"((r)[25]),"=r"((r)[26]),"=r"((r)[27]),"=r"((r)[28]),"=r"((r)[29]),"=r"((r)[30]),"=r"((r)[31]) \
        : "r"(ta))

__device__ __forceinline__ uint32_t elect_one_pred() {
    uint32_t p;
    asm volatile("{ .reg .pred p; elect.sync _|p, 0xFFFFFFFF; selp.b32 %0, 1, 0, p; }" : "=r"(p));
    return p;
}
__device__ __forceinline__ uint64_t mk_desc(uint32_t addr) {
    const uint64_t base = (uint64_t(2) << 61) | (uint64_t(1) << 46) | (uint64_t(64) << 32) | (uint64_t(1) << 16);
    return base | ((uint64_t)(addr >> 4) & 0x3FFF);
}
__device__ __forceinline__ void mma_f16_ss(uint32_t d, uint64_t ad, uint64_t bd,
                                           uint32_t idesc, uint32_t en) {
    asm volatile(
        "{\n\t.reg .pred p;\n\tsetp.ne.u32 p, %4, 0;\n\t"
        "tcgen05.mma.cta_group::1.kind::f16 [%0], %1, %2, %3, {%5,%5,%5,%5}, p;\n\t}"
        :: "r"(d), "l"(ad), "l"(bd), "r"(idesc), "r"(en), "r"(0u) : "memory");
}
__device__ __forceinline__ void bulk_g2s(uint32_t dst, const void* src, uint32_t bytes, uint32_t mbar) {
    asm volatile(
        "cp.async.bulk.shared::cluster.global.mbarrier::complete_tx::bytes [%0], [%1], %2, [%3];"
        :: "r"(dst), "l"(src), "r"(bytes), "r"(mbar) : "memory");
}
#endif  // HAS_TCG

__global__ __launch_bounds__(128, 1) void gemm_tc(const float* __restrict__ bias,
                                                  float* __restrict__ outp, int which) {
#if HAS_TCG
    extern __shared__ char smem[];
    const uint32_t sbase = smem_u32(smem);
    const uint32_t mb0   = sbase + 8;
    const uint32_t done  = sbase + 8 + 16 * NST;
    const uint32_t stg0  = (sbase + 128 + 1023) & ~1023u;

    const int tid = threadIdx.x, wid = tid >> 5, lane = tid & 31;
    const int n0 = blockIdx.x * 256;

    if (wid == 0) TCGEN05_ALLOC(sbase, 512);
    if (tid == 0) {
#pragma unroll
        for (int s = 0; s < NST; s++) {
            MBARRIER_INIT(mb0 + 16 * s, 1);
            MBARRIER_INIT(mb0 + 16 * s + 8, 1);
        }
        MBARRIER_INIT(done, 1);
    }
    __syncthreads();

    uint32_t tmem;
    asm volatile("ld.shared.b32 %0, [%1];" : "=r"(tmem) : "r"(sbase));

    const char* Abase = (const char*)(which < 3 ? g_A16 : g_AO16);
    const char* At0 = Abase + (size_t)(2 * blockIdx.y)     * NKT16 * A_TB;
    const char* At1 = Abase + (size_t)(2 * blockIdx.y + 1) * NKT16 * A_TB;
    const char* Bt  = (const char*)g_W16[which] + (size_t)blockIdx.x * NKT16 * B_TB;

    if (tid == 96) {
        // producer
        int s = 0, ph = 1;
        for (int kt = 0; kt < NKT16; ++kt) {
            MBARRIER_WAIT_PARITY(mb0 + 16 * s + 8, ph);
            MBARRIER_EXPECT_TX(mb0 + 16 * s, STG_B);
            const uint32_t st = stg0 + s * STG_B;
            bulk_g2s(st,                At0 + (size_t)kt * A_TB, A_TB, mb0 + 16 * s);
            bulk_g2s(st + A_TB,         At1 + (size_t)kt * A_TB, A_TB, mb0 + 16 * s);
            bulk_g2s(st + 2 * A_TB,     Bt  + (size_t)kt * B_TB, B_TB, mb0 + 16 * s);
            if (++s == NST) { s = 0; ph ^= 1; }
        }
    } else if (wid == 0) {
        if (elect_one_pred()) {
            int s = 0, ph = 0;
            uint32_t en = 0;
            for (int kt = 0; kt < NKT16; ++kt) {
                MBARRIER_WAIT_PARITY(mb0 + 16 * s, ph);
                const uint32_t st = stg0 + s * STG_B;
                const uint64_t a0 = mk_desc(st);
                const uint64_t a1 = mk_desc(st + A_TB);
                const uint64_t bd = mk_desc(st + 2 * A_TB);
#pragma unroll
                for (int c = 0; c < 4; c++) {   // 4 x K=16 per 64-K tile
                    mma_f16_ss(tmem,       a0 + 2 * c, bd + 2 * c, IDESC_F16, en);
                    mma_f16_ss(tmem + 256, a1 + 2 * c, bd + 2 * c, IDESC_F16, en);
                    en = 1;
                }
                TCGEN05_COMMIT(mb0 + 16 * s + 8);
                if (++s == NST) { s = 0; ph ^= 1; }
            }
            TCGEN05_COMMIT(done);
        }
    }

    MBARRIER_WAIT_PARITY(done, 0);
    TCGEN05_FENCE_AFTER();

    // epilogue: two D tiles (m-tiles 2*by, 2*by+1), 128 threads
#pragma unroll
    for (int dt = 0; dt < 2; dt++) {
        const int m = (2 * blockIdx.y + dt) * 128 + wid * 32 + lane;
        const int b = m >> 9, l = m & 511;
#pragma unroll
        for (int ch = 0; ch < 8; ch++) {
            uint32_t r[32];
            TCGEN05_LD_X32(r, tmem + dt * 256 + ch * 32);
            TCGEN05_WAIT_LD();
            const int cb = n0 + ch * 32;
            if (which < 3) {
                __half* dst = (which == 0) ? g_qh : (which == 1) ? g_kh : g_vh;
                const int h = cb >> 7;
                const size_t rowbase = (((size_t)b * Hq + h) * Lq + l) * HDq;
#pragma unroll
                for (int j = 0; j < 32; j += 2) {
                    const int col = cb + j;
                    *reinterpret_cast<__half2*>(&dst[rowbase + (col & 127)]) =
                        __floats2half2_rn(__uint_as_float(r[j])     + bias[col],
                                          __uint_as_float(r[j + 1]) + bias[col + 1]);
                }
            } else {
#pragma unroll
                for (int j = 0; j < 32; j += 2) {
                    const int col = cb + j;
                    float2 v;
                    v.x = __uint_as_float(r[j])     + bias[col];
                    v.y = __uint_as_float(r[j + 1]) + bias[col + 1];
                    *reinterpret_cast<float2*>(&outp[(size_t)m * Dq + col]) = v;
                }
            }
        }
    }

    __syncthreads();
    if (wid == 0) {
        TCGEN05_RELINQ();
        TCGEN05_DEALLOC(tmem, 512);
    }
#endif  // HAS_TCG
}

// ==========================================================================
// V transpose: [b,h,l,hd] -> [b,h,hd,l]
// ==========================================================================
__global__ void vt_k() {
    __shared__ __half t[32][33];
    const int bh = blockIdx.z;
    const int l0 = blockIdx.x * 32, d0 = blockIdx.y * 32;
    const int tx = threadIdx.x, ty = threadIdx.y;
    const __half* src = g_vh + (size_t)bh * Lq * HDq;
    __half* dst = g_vt + (size_t)bh * HDq * Lq;
#pragma unroll
    for (int j = 0; j < 4; j++) {
        const int l = l0 + ty + j * 8;
        t[ty + j * 8][tx] = src[(size_t)l * HDq + d0 + tx];
    }
    __syncthreads();
#pragma unroll
    for (int j = 0; j < 4; j++) {
        const int d = d0 + ty + j * 8;
        dst[(size_t)d * Lq + l0 + tx] = t[tx][ty + j * 8];
    }
}

// ==========================================================================
// fused flash attention: per CTA one (bh, 128-row m-block). Warps own 16
// full-width rows. Online softmax, fp32 stats, fp16 mma. Writes AO tiles.
// ==========================================================================
__device__ __forceinline__ void fa_load_tile(__half* dst, const __half* src, int ld) {
    const int tid = threadIdx.x;
#pragma unroll
    for (int it = 0; it < 8; it++) {
        const int cid = it * 256 + tid;
        const int r = cid >> 4, c = cid & 15;
        cp_async16(dst + r * 136 + c * 8, src + (size_t)r * ld + c * 8);
    }
}

__global__ __launch_bounds__(256, 1) void fa_k() {
    extern __shared__ __half fsm[];
    __half* Qs = fsm;
    __half* Ks = fsm + FA_TILE_H;       // [2] tiles
    __half* Vs = fsm + 3 * FA_TILE_H;   // [2] tiles

    const int tid = threadIdx.x, w = tid >> 5, lane = tid & 31;
    const int lr = lane >> 2, lc = lane & 3;
    const int mb = blockIdx.x, bh = blockIdx.y;
    const int m0 = mb * 128;

    const __half* Qg = g_qh + ((size_t)bh * Lq + m0) * HDq;
    const __half* Kg = g_kh + (size_t)bh * Lq * HDq;
    const __half* Vg = g_vt + (size_t)bh * HDq * Lq;

    fa_load_tile(Qs, Qg, HDq);
    CP_COMMIT;
    fa_load_tile(Ks, Kg, HDq);
    fa_load_tile(Vs, Vg, Lq);
    CP_COMMIT;

    float oacc[16][4];
#pragma unroll
    for (int nf = 0; nf < 16; nf++)
#pragma unroll
        for (int t = 0; t < 4; t++) oacc[nf][t] = 0.f;
    float mrow[2] = {-1e30f, -1e30f};
    float lrow[2] = {0.f, 0.f};

    const float scale = 0.0883883476483184405501f;  // 1/sqrt(128)

    for (int jb = 0; jb <= mb; jb++) {
        const int buf = jb & 1;
        if (jb < mb) {
            fa_load_tile(Ks + (buf ^ 1) * FA_TILE_H, Kg + (size_t)(jb + 1) * 128 * HDq, HDq);
            fa_load_tile(Vs + (buf ^ 1) * FA_TILE_H, Vg + (jb + 1) * 128, Lq);
            CP_COMMIT;
            CP_WAIT1;
        } else {
            CP_WAIT0;
        }
        __syncthreads();

        const uint32_t* qs = (const uint32_t*)Qs;
        const uint32_t* ks = (const uint32_t*)(Ks + buf * FA_TILE_H);
        const uint32_t* vs = (const uint32_t*)(Vs + buf * FA_TILE_H);

        // ---- S = Q @ K^T ----
        float sacc[16][4];
#pragma unroll
        for (int nf = 0; nf < 16; nf++)
#pragma unroll
            for (int t = 0; t < 4; t++) sacc[nf][t] = 0.f;
#pragma unroll
        for (int kc = 0; kc < 8; kc++) {
            uint32_t a[4];
            const int ra = (w * 16 + lr) * 68 + kc * 8 + lc;
            a[0] = qs[ra];           a[1] = qs[ra + 8 * 68];
            a[2] = qs[ra + 4];       a[3] = qs[ra + 8 * 68 + 4];
#pragma unroll
            for (int nf = 0; nf < 16; nf++) {
                const int rb = (nf * 8 + lr) * 68 + kc * 8 + lc;
                uint32_t b[2] = {ks[rb], ks[rb + 4]};
                mma_f16(sacc[nf], a, b);
            }
        }

        // ---- scale + causal mask (diagonal block only) ----
        if (jb == mb) {
#pragma unroll
            for (int nf = 0; nf < 16; nf++)
#pragma unroll
                for (int t = 0; t < 4; t++) {
                    const int col = nf * 8 + 2 * lc + (t & 1);
                    const int row = w * 16 + lr + 8 * (t >> 1);
                    sacc[nf][t] = (col <= row) ? sacc[nf][t] * scale : -1e30f;
                }
        } else {
#pragma unroll
            for (int nf = 0; nf < 16; nf++)
#pragma unroll
                for (int t = 0; t < 4; t++) sacc[nf][t] *= scale;
        }

        // ---- online softmax update ----
        float tmax[2] = {-1e30f, -1e30f};
#pragma unroll
        for (int nf = 0; nf < 16; nf++) {
            tmax[0] = fmaxf(tmax[0], fmaxf(sacc[nf][0], sacc[nf][1]));
            tmax[1] = fmaxf(tmax[1], fmaxf(sacc[nf][2], sacc[nf][3]));
        }
#pragma unroll
        for (int o = 1; o <= 2; o <<= 1) {
            tmax[0] = fmaxf(tmax[0], __shfl_xor_sync(0xffffffffu, tmax[0], o));
            tmax[1] = fmaxf(tmax[1], __shfl_xor_sync(0xffffffffu, tmax[1], o));
        }
        float mnew[2], f[2];
#pragma unroll
        for (int rr = 0; rr < 2; rr++) {
            mnew[rr] = fmaxf(mrow[rr], tmax[rr]);
            f[rr] = __expf(mrow[rr] - mnew[rr]);
            mrow[rr] = mnew[rr];
        }
        float lsum[2] = {0.f, 0.f};
#pragma unroll
        for (int nf = 0; nf < 16; nf++) {
            sacc[nf][0] = __expf(sacc[nf][0] - mnew[0]);
            sacc[nf][1] = __expf(sacc[nf][1] - mnew[0]);
            sacc[nf][2] = __expf(sacc[nf][2] - mnew[1]);
            sacc[nf][3] = __expf(sacc[nf][3] - mnew[1]);
            lsum[0] += sacc[nf][0] + sacc[nf][1];
            lsum[1] += sacc[nf][2] + sacc[nf][3];
        }
#pragma unroll
        for (int o = 1; o <= 2; o <<= 1) {
            lsum[0] += __shfl_xor_sync(0xffffffffu, lsum[0], o);
            lsum[1] += __shfl_xor_sync(0xffffffffu, lsum[1], o);
        }
        lrow[0] = lrow[0] * f[0] + lsum[0];
        lrow[1] = lrow[1] * f[1] + lsum[1];
#pragma unroll
        for (int nf = 0; nf < 16; nf++) {
            oacc[nf][0] *= f[0]; oacc[nf][1] *= f[0];
            oacc[nf][2] *= f[1]; oacc[nf][3] *= f[1];
        }

        // ---- O += P @ V^T ----
#pragma unroll
        for (int kc = 0; kc < 8; kc++) {
            uint32_t pa[4];
            pa[0] = h2u(sacc[2 * kc][0],     sacc[2 * kc][1]);
            pa[1] = h2u(sacc[2 * kc][2],     sacc[2 * kc][3]);
            pa[2] = h2u(sacc[2 * kc + 1][0], sacc[2 * kc + 1][1]);
            pa[3] = h2u(sacc[2 * kc + 1][2], sacc[2 * kc + 1][3]);
#pragma unroll
            for (int nf = 0; nf < 16; nf++) {
                const int rb = (nf * 8 + lr) * 68 + kc * 8 + lc;
                uint32_t b[2] = {vs[rb], vs[rb + 4]};
                mma_f16(oacc[nf], pa, b);
            }
        }
        __syncthreads();
    }

    // ---- finalize: O /= l, write tiled+swizzled AO ----
    const float inv0 = 1.f / lrow[0], inv1 = 1.f / lrow[1];
    const int b = bh >> 5, h = bh & 31;
#pragma unroll
    for (int nf = 0; nf < 16; nf++) {
#pragma unroll
        for (int rr = 0; rr < 2; rr++) {
            const int m = m0 + w * 16 + lr + 8 * rr;      // l index
            const int d = nf * 8 + 2 * lc;                // hd index (even)
            const float inv = rr ? inv1 : inv0;
            const uint32_t hv = h2u(oacc[nf][rr * 2] * inv, oacc[nf][rr * 2 + 1] * inv);
            const int R = b * Lq + m;
            const int C = h * HDq + d;
            const int mb2 = R >> 7, rl = R & 127, kt = C >> 6, cc = C & 63;
            char* tb = (char*)g_AO16 + (size_t)(mb2 * NKT16 + kt) * A_TB;
            *reinterpret_cast<uint32_t*>(tb + swz((uint32_t)(rl * 128 + cc * 2))) = hv;
        }
    }
}

// ==========================================================================
extern "C" void kernel_launch(void* const* d_in, const int* in_sizes, int n_in,
                              void* d_out, int out_size) {
    const float* x  = (const float*)d_in[0];
    const float* Wq = (const float*)d_in[1];
    const float* bq = (const float*)d_in[2];
    const float* Wk = (const float*)d_in[3];
    const float* bk = (const float*)d_in[4];
    const float* Wv = (const float*)d_in[5];
    const float* bv = (const float*)d_in[6];
    const float* Wo = (const float*)d_in[7];
    const float* bo = (const float*)d_in[8];
    float* out = (float*)d_out;

    cudaFuncSetAttribute(gemm_tc, cudaFuncAttributeMaxDynamicSharedMemorySize, GEMM_SMEM);
    cudaFuncSetAttribute(fa_k,    cudaFuncAttributeMaxDynamicSharedMemorySize, FA_SMEM);

    // 1) prepass: fp16 + tile + swizzle
    prep_x16<<<(int)((size_t)BLq * Dq / 8 / 256), 256>>>((const float4*)x);
    prep_w16<<<(int)((size_t)Dq * Dq / 8 / 256), 256>>>((const float4*)Wq, 0);
    prep_w16<<<(int)((size_t)Dq * Dq / 8 / 256), 256>>>((const float4*)Wk, 1);
    prep_w16<<<(int)((size_t)Dq * Dq / 8 / 256), 256>>>((const float4*)Wv, 2);
    prep_w16<<<(int)((size_t)Dq * Dq / 8 / 256), 256>>>((const float4*)Wo, 3);

    // 2) Q/K/V projections (tcgen05 fp16, 256x256 tiles)
    dim3 gg(Dq / 256, BLq / 256);   // (16, 64)
    gemm_tc<<<gg, 128, GEMM_SMEM>>>(bq, nullptr, 0);
    gemm_tc<<<gg, 128, GEMM_SMEM>>>(bk, nullptr, 1);
    gemm_tc<<<gg, 128, GEMM_SMEM>>>(bv, nullptr, 2);

    // 3) attention: V transpose + fused flash attention
    vt_k<<<dim3(16, 4, BHq), dim3(32, 8)>>>();
    fa_k<<<dim3(4, BHq), 256, FA_SMEM>>>();

    // 4) output projection
    gemm_tc<<<gg, 128, GEMM_SMEM>>>(bo, out, 3);
}